// round 2
// baseline (speedup 1.0000x reference)
#include <cuda_runtime.h>

#define N_NODES 100000
#define N_EDGES 3200000

// Per-node 2-float projected aggregate: z[i*2+c] = sum_{edges e with col==i} edge_attr[e] . W1[3:19, c]
__device__ float g_z[2 * N_NODES];

__global__ void zero_kernel() {
    int i = blockIdx.x * blockDim.x + threadIdx.x;
    if (i < 2 * N_NODES) g_z[i] = 0.0f;
}

__global__ void __launch_bounds__(256) edge_kernel(
    const float4* __restrict__ ea,        // edge_attr as float4[N_EDGES*4]
    const int* __restrict__ col,          // edge_index row 1 (dst nodes), int32
    const float* __restrict__ W1)         // [19,2] row-major
{
    // Hoist the edge slice of W1 (rows 3..18, cols 0/1) into registers.
    // Uniform addresses -> warp-broadcast L1 hits.
    float w0[16], w1[16];
#pragma unroll
    for (int k = 0; k < 16; k++) {
        w0[k] = __ldg(&W1[(3 + k) * 2 + 0]);
        w1[k] = __ldg(&W1[(3 + k) * 2 + 1]);
    }

    int e = blockIdx.x * blockDim.x + threadIdx.x;
    if (e >= N_EDGES) return;

    const float4 a = ea[e * 4 + 0];
    const float4 b = ea[e * 4 + 1];
    const float4 c = ea[e * 4 + 2];
    const float4 d = ea[e * 4 + 3];

    float p0 = a.x * w0[0]  + a.y * w0[1]  + a.z * w0[2]  + a.w * w0[3]
             + b.x * w0[4]  + b.y * w0[5]  + b.z * w0[6]  + b.w * w0[7]
             + c.x * w0[8]  + c.y * w0[9]  + c.z * w0[10] + c.w * w0[11]
             + d.x * w0[12] + d.y * w0[13] + d.z * w0[14] + d.w * w0[15];

    float p1 = a.x * w1[0]  + a.y * w1[1]  + a.z * w1[2]  + a.w * w1[3]
             + b.x * w1[4]  + b.y * w1[5]  + b.z * w1[6]  + b.w * w1[7]
             + c.x * w1[8]  + c.y * w1[9]  + c.z * w1[10] + c.w * w1[11]
             + d.x * w1[12] + d.y * w1[13] + d.z * w1[14] + d.w * w1[15];

    int node = col[e];
    if ((unsigned)node < (unsigned)N_NODES) {
        atomicAdd(&g_z[node * 2 + 0], p0);
        atomicAdd(&g_z[node * 2 + 1], p1);
    }
}

__global__ void __launch_bounds__(256) node_kernel(
    const float* __restrict__ x,
    const float* __restrict__ W1,
    const float* __restrict__ b1,
    const float* __restrict__ W2,
    const float* __restrict__ b2,
    float* __restrict__ out)
{
    int i = blockIdx.x * blockDim.x + threadIdx.x;
    if (i >= N_NODES) return;

    const float x0 = x[i * 3 + 0];
    const float x1 = x[i * 3 + 1];
    const float x2 = x[i * 3 + 2];

    // h = [x, agg] @ W1 + b1; agg part already projected into g_z.
    float h0 = b1[0] + x0 * W1[0] + x1 * W1[2] + x2 * W1[4] + g_z[i * 2 + 0];
    float h1 = b1[1] + x0 * W1[1] + x1 * W1[3] + x2 * W1[5] + g_z[i * 2 + 1];
    h0 = fmaxf(h0, 0.0f);
    h1 = fmaxf(h1, 0.0f);

    // Only output column 2 of the MLP survives. W2 is [2,3] row-major.
    const float o2 = h0 * W2[2] + h1 * W2[5] + b2[2] + x2;

    const float vi = x0, s1 = x1, s2 = x2;

    const float n1 = (powf(0.7660379f, s2 / 0.3038425f + s1)
                      + powf(0.12117091f, s1) / (-0.7256157f))
                     * powf(1.2125463f, vi) + 0.12262904f;

    const float t = s2 + (s1 + (-3.283101f) - vi / 0.79082423f) * 0.31992579f;
    // powf(.,.) > 0 so log argument >= 1.4462701 -> always finite.
    const float n1_n2 = 0.7872602f - sqrtf(logf(powf(0.1562228f, t) + 1.4462701f));

    out[i * 3 + 0] = n1 + x0;
    out[i * 3 + 1] = (n1_n2 - n1) + x1;
    out[i * 3 + 2] = o2;
}

extern "C" void kernel_launch(void* const* d_in, const int* in_sizes, int n_in,
                              void* d_out, int out_size) {
    // Inputs (metadata order): 0:x 1:edge_attr 2:u 3:W1 4:b1 5:W2 6:b2 7:edge_index 8:batch
    const float*  x    = (const float*)d_in[0];
    const float4* ea   = (const float4*)d_in[1];
    const float*  W1   = (const float*)d_in[3];
    const float*  b1   = (const float*)d_in[4];
    const float*  W2   = (const float*)d_in[5];
    const float*  b2   = (const float*)d_in[6];
    const int*    eidx = (const int*)d_in[7];   // int64 in reference -> int32 on device
    float*        out  = (float*)d_out;

    const int* col = eidx + N_EDGES;  // edge_index[1, :]

    zero_kernel<<<(2 * N_NODES + 255) / 256, 256>>>();
    edge_kernel<<<(N_EDGES + 255) / 256, 256>>>(ea, col, W1);
    node_kernel<<<(N_NODES + 255) / 256, 256>>>(x, W1, b1, W2, b2, out);
}

// round 3
// speedup vs baseline: 1.1840x; 1.1840x over previous
#include <cuda_runtime.h>

#define N_NODES 100000
#define N_EDGES 3200000

// Per-node projected aggregate: g_z[i] = sum over edges e with col==i of
// (edge_attr[e] . W1[3:19, 0], edge_attr[e] . W1[3:19, 1]).
// Invariant: zero at kernel_launch entry. __device__ globals are
// zero-initialized at load; node_kernel re-zeros after consuming, so the
// invariant holds across graph replays.
__device__ float2 g_z[N_NODES];

__global__ void __launch_bounds__(256) edge_kernel(
    const float4* __restrict__ ea,        // edge_attr as float4[N_EDGES*4]
    const int* __restrict__ col,          // edge_index row 1 (dst nodes), int32
    const float* __restrict__ W1)         // [19,2] row-major
{
    // Hoist the edge slice of W1 (rows 3..18, cols 0/1) into registers.
    float w0[16], w1[16];
#pragma unroll
    for (int k = 0; k < 16; k++) {
        w0[k] = __ldg(&W1[(3 + k) * 2 + 0]);
        w1[k] = __ldg(&W1[(3 + k) * 2 + 1]);
    }

    int e = blockIdx.x * blockDim.x + threadIdx.x;
    if (e >= N_EDGES) return;

    const float4 a = ea[e * 4 + 0];
    const float4 b = ea[e * 4 + 1];
    const float4 c = ea[e * 4 + 2];
    const float4 d = ea[e * 4 + 3];

    float p0 = a.x * w0[0]  + a.y * w0[1]  + a.z * w0[2]  + a.w * w0[3]
             + b.x * w0[4]  + b.y * w0[5]  + b.z * w0[6]  + b.w * w0[7]
             + c.x * w0[8]  + c.y * w0[9]  + c.z * w0[10] + c.w * w0[11]
             + d.x * w0[12] + d.y * w0[13] + d.z * w0[14] + d.w * w0[15];

    float p1 = a.x * w1[0]  + a.y * w1[1]  + a.z * w1[2]  + a.w * w1[3]
             + b.x * w1[4]  + b.y * w1[5]  + b.z * w1[6]  + b.w * w1[7]
             + c.x * w1[8]  + c.y * w1[9]  + c.z * w1[10] + c.w * w1[11]
             + d.x * w1[12] + d.y * w1[13] + d.z * w1[14] + d.w * w1[15];

    int node = col[e];
    if ((unsigned)node < (unsigned)N_NODES) {
        // Single vector atomic (RED.ADD.F32x2) instead of two scalar REDs.
        atomicAdd(&g_z[node], make_float2(p0, p1));
    }
}

__global__ void __launch_bounds__(256) node_kernel(
    const float* __restrict__ x,
    const float* __restrict__ W1,
    const float* __restrict__ b1,
    const float* __restrict__ W2,
    const float* __restrict__ b2,
    float* __restrict__ out)
{
    int i = blockIdx.x * blockDim.x + threadIdx.x;
    if (i >= N_NODES) return;

    const float x0 = x[i * 3 + 0];
    const float x1 = x[i * 3 + 1];
    const float x2 = x[i * 3 + 2];

    const float2 z = g_z[i];
    g_z[i] = make_float2(0.0f, 0.0f);   // restore zero-invariant for next replay

    // h = [x, agg] @ W1 + b1; agg part already projected into z.
    float h0 = b1[0] + x0 * W1[0] + x1 * W1[2] + x2 * W1[4] + z.x;
    float h1 = b1[1] + x0 * W1[1] + x1 * W1[3] + x2 * W1[5] + z.y;
    h0 = fmaxf(h0, 0.0f);
    h1 = fmaxf(h1, 0.0f);

    // Only output column 2 of the MLP survives. W2 is [2,3] row-major.
    const float o2 = h0 * W2[2] + h1 * W2[5] + b2[2] + x2;

    const float vi = x0, s1 = x1, s2 = x2;

    const float n1 = (powf(0.7660379f, s2 / 0.3038425f + s1)
                      + powf(0.12117091f, s1) / (-0.7256157f))
                     * powf(1.2125463f, vi) + 0.12262904f;

    const float t = s2 + (s1 + (-3.283101f) - vi / 0.79082423f) * 0.31992579f;
    const float n1_n2 = 0.7872602f - sqrtf(logf(powf(0.1562228f, t) + 1.4462701f));

    out[i * 3 + 0] = n1 + x0;
    out[i * 3 + 1] = (n1_n2 - n1) + x1;
    out[i * 3 + 2] = o2;
}

extern "C" void kernel_launch(void* const* d_in, const int* in_sizes, int n_in,
                              void* d_out, int out_size) {
    // Inputs: 0:x 1:edge_attr 2:u 3:W1 4:b1 5:W2 6:b2 7:edge_index 8:batch
    const float*  x    = (const float*)d_in[0];
    const float4* ea   = (const float4*)d_in[1];
    const float*  W1   = (const float*)d_in[3];
    const float*  b1   = (const float*)d_in[4];
    const float*  W2   = (const float*)d_in[5];
    const float*  b2   = (const float*)d_in[6];
    const int*    eidx = (const int*)d_in[7];   // int64 in reference -> int32 on device
    float*        out  = (float*)d_out;

    const int* col = eidx + N_EDGES;  // edge_index[1, :]

    edge_kernel<<<(N_EDGES + 255) / 256, 256>>>(ea, col, W1);
    node_kernel<<<(N_NODES + 255) / 256, 256>>>(x, W1, b1, W2, b2, out);
}